// round 5
// baseline (speedup 1.0000x reference)
#include <cuda_runtime.h>

// ---------------------------------------------------------------------------
// MHSA with (bug-faithful) RPE:  per (b,h):
//   L = Q K^T / 14  +  C_h Q        (C_h = (rel_h+rel_w) reshaped, 196x196)
//   A = softmax_rows(L)
//   O = A V   -> (b,n,c) -> out = O Wo^T + bo
// All fp32. Scratch in __device__ globals (no allocation anywhere).
// ---------------------------------------------------------------------------

constexpr int Bn = 256;   // batch
constexpr int Tn = 196;   // tokens (== HW == D)
constexpr int Cn = 784;   // channels
constexpr int Hn = 4;     // heads
constexpr int Dn = 196;   // head dim
constexpr int HGTn = 14;
constexpr int WIDn = 14;
constexpr int BHn = Bn * Hn;          // 1024
constexpr int SQn = Tn * Dn;          // 38416 (per-bh matrix)
constexpr int Rows = Bn * Tn;         // 50176

__device__ float g_q[(size_t)BHn * SQn];   // [b*H+h][n][d]
__device__ float g_k[(size_t)BHn * SQn];
__device__ float g_v[(size_t)BHn * SQn];
__device__ float g_l[(size_t)BHn * SQn];   // logits, then attn (in place)
__device__ float g_o[(size_t)Rows * Cn];   // (b, n, c) pre-output-proj
__device__ float g_cp[(size_t)Hn * SQn];   // [h][p][t]

static __device__ __forceinline__ float4 f4zero() { return make_float4(0.f, 0.f, 0.f, 0.f); }

// ---------------------------------------------------------------------------
// cp[h][p][t] = rel_h[h, t, p/14] + rel_w[h, t, p%14]
// rel_h: (1,H,D,14,1) flat (h*D + t)*14 + i ;  rel_w: (1,H,D,1,14) same stride
// ---------------------------------------------------------------------------
__global__ void build_cp_kernel(const float* __restrict__ rel_h,
                                const float* __restrict__ rel_w)
{
    int idx = blockIdx.x * blockDim.x + threadIdx.x;
    if (idx >= Hn * SQn) return;
    int t = idx % Dn;
    int p = (idx / Dn) % Tn;
    int h = idx / (Dn * Tn);
    g_cp[idx] = rel_h[(h * Dn + t) * HGTn + (p / WIDn)]
              + rel_w[(h * Dn + t) * WIDn + (p % WIDn)];
}

// ---------------------------------------------------------------------------
// NT SGEMM:  out[r][j] = bias[j] + sum_k A[r][k] * W[j][k]
// M = 50176 (exact /128), N = 784 (13 col tiles of 64, predicated), K = 784.
// CTA tile 128x64, BK=16, 256 threads, 8x4 per-thread micro-tile.
// OUT_SEL: 0 -> plain row-major to outp (A taken from g_o)
//          1/2/3 -> scatter to g_q/g_k/g_v in [b*H+h][n][d] layout
// ---------------------------------------------------------------------------
template <int OUT_SEL>
__global__ void __launch_bounds__(256) proj_kernel(const float* __restrict__ Ain,
                                                   const float* __restrict__ W,
                                                   const float* __restrict__ bias,
                                                   float* __restrict__ outp)
{
    const float* __restrict__ A = (OUT_SEL == 0) ? g_o : Ain;

    __shared__ float As[16][132];   // [k][m], padded
    __shared__ float Bs[16][68];    // [k][n], padded

    const int tid = threadIdx.x;
    const int m0 = blockIdx.y * 128;
    const int n0 = blockIdx.x * 64;
    const int ty = tid >> 4;        // 0..15
    const int tx = tid & 15;        // 0..15
    const int lr = tid >> 2;        // 0..63
    const int lc = (tid & 3) * 4;   // 0,4,8,12 (k sub-offset)

    float acc[8][4];
#pragma unroll
    for (int i = 0; i < 8; i++)
#pragma unroll
        for (int j = 0; j < 4; j++) acc[i][j] = 0.f;

    for (int kt = 0; kt < 49; ++kt) {
        const int k0 = kt * 16;
        float4 a0 = *(const float4*)(A + (size_t)(m0 + lr) * Cn + k0 + lc);
        float4 a1 = *(const float4*)(A + (size_t)(m0 + lr + 64) * Cn + k0 + lc);
        float4 b0 = (n0 + lr < Cn)
                        ? *(const float4*)(W + (size_t)(n0 + lr) * Cn + k0 + lc)
                        : f4zero();
        __syncthreads();
        As[lc + 0][lr] = a0.x; As[lc + 1][lr] = a0.y; As[lc + 2][lr] = a0.z; As[lc + 3][lr] = a0.w;
        As[lc + 0][lr + 64] = a1.x; As[lc + 1][lr + 64] = a1.y; As[lc + 2][lr + 64] = a1.z; As[lc + 3][lr + 64] = a1.w;
        Bs[lc + 0][lr] = b0.x; Bs[lc + 1][lr] = b0.y; Bs[lc + 2][lr] = b0.z; Bs[lc + 3][lr] = b0.w;
        __syncthreads();
#pragma unroll
        for (int k = 0; k < 16; k++) {
            float a[8], b[4];
#pragma unroll
            for (int i = 0; i < 8; i++) a[i] = As[k][i * 16 + ty];
#pragma unroll
            for (int j = 0; j < 4; j++) b[j] = Bs[k][j * 16 + tx];
#pragma unroll
            for (int i = 0; i < 8; i++)
#pragma unroll
                for (int j = 0; j < 4; j++) acc[i][j] = fmaf(a[i], b[j], acc[i][j]);
        }
    }

#pragma unroll
    for (int j = 0; j < 4; j++) {
        int gc = n0 + j * 16 + tx;
        if (gc >= Cn) continue;
        float bv = bias[gc];
#pragma unroll
        for (int i = 0; i < 8; i++) {
            int gr = m0 + i * 16 + ty;
            float val = acc[i][j] + bv;
            if (OUT_SEL == 0) {
                outp[(size_t)gr * Cn + gc] = val;
            } else {
                int b = gr / Tn, n = gr % Tn;
                int h = gc / Dn, dd = gc % Dn;
                float* dst = (OUT_SEL == 1) ? g_q : (OUT_SEL == 2) ? g_k : g_v;
                dst[((size_t)(b * Hn + h) * Tn + n) * Dn + dd] = val;
            }
        }
    }
}

// ---------------------------------------------------------------------------
// Logits: per bh, L[p][m] = sum_t Q[p][t]*K[m][t]/14 + sum_t C[p][t]*Q[t][m]
// Grid (4,4,1024): 64x64 tile per CTA, BK=28 (196 = 7*28), dual-accumulate.
// ---------------------------------------------------------------------------
__global__ void __launch_bounds__(256) logits_kernel()
{
    const int bh = blockIdx.z;
    const int h  = bh & 3;
    const int p0 = blockIdx.y * 64;
    const int m0 = blockIdx.x * 64;
    const float* __restrict__ Q  = g_q  + (size_t)bh * SQn;
    const float* __restrict__ Kp = g_k  + (size_t)bh * SQn;
    const float* __restrict__ CP = g_cp + (size_t)h  * SQn;

    __shared__ float Aq[28][65];   // [t][p]
    __shared__ float Ac[28][65];   // [t][p]
    __shared__ float Bk[28][65];   // [t][m], pre-scaled by 1/14
    __shared__ float Bq[28][68];   // [t][m] from Q^T side

    const int tid = threadIdx.x;
    const int ty = tid >> 4, tx = tid & 15;
    const float invs = 1.0f / 14.0f;

    float acc[4][4];
#pragma unroll
    for (int i = 0; i < 4; i++)
#pragma unroll
        for (int j = 0; j < 4; j++) acc[i][j] = 0.f;

    for (int kt = 0; kt < 7; ++kt) {
        const int t0 = kt * 28;
        float4 qa[2], ca[2], kb[2], qb[2];
#pragma unroll
        for (int u = 0; u < 2; ++u) {
            int f = tid + u * 256;
            if (f < 448) {
                int row = f / 7, c4 = (f % 7) * 4;
                int pr = p0 + row, mr = m0 + row;
                if (pr < Tn) {
                    qa[u] = *(const float4*)(Q  + pr * Dn + t0 + c4);
                    ca[u] = *(const float4*)(CP + pr * Dn + t0 + c4);
                } else { qa[u] = f4zero(); ca[u] = f4zero(); }
                kb[u] = (mr < Tn) ? *(const float4*)(Kp + mr * Dn + t0 + c4) : f4zero();
                int c = f >> 4, n4 = (f & 15) * 4;
                qb[u] = (m0 + n4 < Tn) ? *(const float4*)(Q + (t0 + c) * Dn + m0 + n4)
                                       : f4zero();
            }
        }
        __syncthreads();
#pragma unroll
        for (int u = 0; u < 2; ++u) {
            int f = tid + u * 256;
            if (f < 448) {
                int row = f / 7, kc = (f % 7) * 4;
                Aq[kc + 0][row] = qa[u].x; Aq[kc + 1][row] = qa[u].y;
                Aq[kc + 2][row] = qa[u].z; Aq[kc + 3][row] = qa[u].w;
                Ac[kc + 0][row] = ca[u].x; Ac[kc + 1][row] = ca[u].y;
                Ac[kc + 2][row] = ca[u].z; Ac[kc + 3][row] = ca[u].w;
                Bk[kc + 0][row] = kb[u].x * invs; Bk[kc + 1][row] = kb[u].y * invs;
                Bk[kc + 2][row] = kb[u].z * invs; Bk[kc + 3][row] = kb[u].w * invs;
                int c = f >> 4, n4 = (f & 15) * 4;
                *(float4*)&Bq[c][n4] = qb[u];
            }
        }
        __syncthreads();
#pragma unroll
        for (int k = 0; k < 28; k++) {
            float a1[4], a2[4], b1[4], b2[4];
#pragma unroll
            for (int i = 0; i < 4; i++) { a1[i] = Aq[k][i * 16 + ty]; a2[i] = Ac[k][i * 16 + ty]; }
#pragma unroll
            for (int j = 0; j < 4; j++) { b1[j] = Bk[k][j * 16 + tx]; b2[j] = Bq[k][j * 16 + tx]; }
#pragma unroll
            for (int i = 0; i < 4; i++)
#pragma unroll
                for (int j = 0; j < 4; j++)
                    acc[i][j] = fmaf(a2[i], b2[j], fmaf(a1[i], b1[j], acc[i][j]));
        }
    }

    float* __restrict__ L = g_l + (size_t)bh * SQn;
#pragma unroll
    for (int i = 0; i < 4; i++) {
        int p = p0 + i * 16 + ty;
        if (p >= Tn) continue;
#pragma unroll
        for (int j = 0; j < 4; j++) {
            int m = m0 + j * 16 + tx;
            if (m < Tn) L[p * Tn + m] = acc[i][j];
        }
    }
}

// ---------------------------------------------------------------------------
// Row softmax over 196 elements, one warp per row, in place in g_l.
// ---------------------------------------------------------------------------
__global__ void __launch_bounds__(256) softmax_kernel()
{
    int gw = (blockIdx.x * blockDim.x + threadIdx.x) >> 5;
    int lane = threadIdx.x & 31;
    if (gw >= BHn * Tn) return;
    float* __restrict__ row = g_l + (size_t)gw * Tn;

    float v[7];
    float mx = -3.0e38f;
#pragma unroll
    for (int w = 0; w < 7; w++) {
        int idx = lane + w * 32;
        v[w] = (idx < Tn) ? row[idx] : -3.0e38f;
        mx = fmaxf(mx, v[w]);
    }
#pragma unroll
    for (int o = 16; o > 0; o >>= 1) mx = fmaxf(mx, __shfl_xor_sync(0xffffffffu, mx, o));

    float s = 0.f;
#pragma unroll
    for (int w = 0; w < 7; w++) {
        int idx = lane + w * 32;
        float e = (idx < Tn) ? __expf(v[w] - mx) : 0.f;
        v[w] = e; s += e;
    }
#pragma unroll
    for (int o = 16; o > 0; o >>= 1) s += __shfl_xor_sync(0xffffffffu, s, o);

    float inv = 1.0f / s;
#pragma unroll
    for (int w = 0; w < 7; w++) {
        int idx = lane + w * 32;
        if (idx < Tn) row[idx] = v[w] * inv;
    }
}

// ---------------------------------------------------------------------------
// O[bh][p][dd] = sum_m A[bh][p][m] * V[bh][m][dd]   -> g_o in (b,n,c) layout
// ---------------------------------------------------------------------------
__global__ void __launch_bounds__(256) av_kernel()
{
    const int bh = blockIdx.z;
    const int b = bh >> 2, h = bh & 3;
    const int p0 = blockIdx.y * 64;
    const int d0 = blockIdx.x * 64;
    const float* __restrict__ Att = g_l + (size_t)bh * SQn;
    const float* __restrict__ V   = g_v + (size_t)bh * SQn;

    __shared__ float As[28][65];   // [m][p]
    __shared__ float Bs[28][68];   // [m][dd]

    const int tid = threadIdx.x;
    const int ty = tid >> 4, tx = tid & 15;

    float acc[4][4];
#pragma unroll
    for (int i = 0; i < 4; i++)
#pragma unroll
        for (int j = 0; j < 4; j++) acc[i][j] = 0.f;

    for (int kt = 0; kt < 7; ++kt) {
        const int t0 = kt * 28;
        float4 av4[2], bv4[2];
#pragma unroll
        for (int u = 0; u < 2; ++u) {
            int f = tid + u * 256;
            if (f < 448) {
                int row = f / 7, c4 = (f % 7) * 4;
                int pr = p0 + row;
                av4[u] = (pr < Tn) ? *(const float4*)(Att + pr * Tn + t0 + c4) : f4zero();
                int c = f >> 4, n4 = (f & 15) * 4;
                bv4[u] = (d0 + n4 < Dn) ? *(const float4*)(V + (t0 + c) * Dn + d0 + n4)
                                        : f4zero();
            }
        }
        __syncthreads();
#pragma unroll
        for (int u = 0; u < 2; ++u) {
            int f = tid + u * 256;
            if (f < 448) {
                int row = f / 7, kc = (f % 7) * 4;
                As[kc + 0][row] = av4[u].x; As[kc + 1][row] = av4[u].y;
                As[kc + 2][row] = av4[u].z; As[kc + 3][row] = av4[u].w;
                int c = f >> 4, n4 = (f & 15) * 4;
                *(float4*)&Bs[c][n4] = bv4[u];
            }
        }
        __syncthreads();
#pragma unroll
        for (int k = 0; k < 28; k++) {
            float a[4], bb[4];
#pragma unroll
            for (int i = 0; i < 4; i++) a[i] = As[k][i * 16 + ty];
#pragma unroll
            for (int j = 0; j < 4; j++) bb[j] = Bs[k][j * 16 + tx];
#pragma unroll
            for (int i = 0; i < 4; i++)
#pragma unroll
                for (int j = 0; j < 4; j++) acc[i][j] = fmaf(a[i], bb[j], acc[i][j]);
        }
    }

#pragma unroll
    for (int i = 0; i < 4; i++) {
        int p = p0 + i * 16 + ty;
        if (p >= Tn) continue;
#pragma unroll
        for (int j = 0; j < 4; j++) {
            int dd = d0 + j * 16 + tx;
            if (dd < Dn)
                g_o[(size_t)(b * Tn + p) * Cn + h * Dn + dd] = acc[i][j];
        }
    }
}

// ---------------------------------------------------------------------------
extern "C" void kernel_launch(void* const* d_in, const int* in_sizes, int n_in,
                              void* d_out, int out_size)
{
    const float* x    = (const float*)d_in[0];
    const float* Wq   = (const float*)d_in[1];
    const float* bq   = (const float*)d_in[2];
    const float* Wk   = (const float*)d_in[3];
    const float* bk   = (const float*)d_in[4];
    const float* Wv   = (const float*)d_in[5];
    const float* bv   = (const float*)d_in[6];
    const float* Wo   = (const float*)d_in[7];
    const float* bo   = (const float*)d_in[8];
    const float* relh = (const float*)d_in[9];
    const float* relw = (const float*)d_in[10];
    float* out = (float*)d_out;

    build_cp_kernel<<<(Hn * SQn + 255) / 256, 256>>>(relh, relw);

    dim3 pg(13, 392);   // 13 col tiles of 64 (784 predicated), 392 row tiles of 128
    proj_kernel<1><<<pg, 256>>>(x, Wq, bq, nullptr);
    proj_kernel<2><<<pg, 256>>>(x, Wk, bk, nullptr);
    proj_kernel<3><<<pg, 256>>>(x, Wv, bv, nullptr);

    logits_kernel<<<dim3(4, 4, BHn), 256>>>();
    softmax_kernel<<<(BHn * Tn) / 8, 256>>>();
    av_kernel<<<dim3(4, 4, BHn), 256>>>();

    proj_kernel<0><<<pg, 256>>>(nullptr, Wo, bo, out);
}

// round 9
// speedup vs baseline: 1.2151x; 1.2151x over previous
#include <cuda_runtime.h>

// ---------------------------------------------------------------------------
// MHSA with (bug-faithful) RPE, fp32, packed-f32x2 FFMA2 inner loops.
//   per (b,h):  L = Q K^T / 14 + C_h Q ; A = softmax(L) ; O = A V
//   out = O Wo^T + bo
// ---------------------------------------------------------------------------

typedef unsigned long long u64;

constexpr int Bn = 256;
constexpr int Tn = 196;
constexpr int Cn = 784;
constexpr int Hn = 4;
constexpr int Dn = 196;
constexpr int HGTn = 14;
constexpr int WIDn = 14;
constexpr int BHn = Bn * Hn;     // 1024
constexpr int SQn = Tn * Dn;     // 38416
constexpr int Rows = Bn * Tn;    // 50176

__device__ float g_q[(size_t)BHn * SQn];
__device__ float g_k[(size_t)BHn * SQn];
__device__ float g_v[(size_t)BHn * SQn];
__device__ float g_l[(size_t)BHn * SQn];
__device__ float g_o[(size_t)Rows * Cn];
__device__ float g_cp[(size_t)Hn * SQn];

static __device__ __forceinline__ float4 f4zero() { return make_float4(0.f, 0.f, 0.f, 0.f); }

static __device__ __forceinline__ u64 dup2(float v) {
    u64 r; asm("mov.b64 %0, {%1,%1};" : "=l"(r) : "f"(v)); return r;
}
static __device__ __forceinline__ void ffma2(u64& d, u64 a, u64 b) {
    asm("fma.rn.f32x2 %0, %1, %2, %3;" : "=l"(d) : "l"(a), "l"(b), "l"(d));
}
static __device__ __forceinline__ float2 unpack2(u64 p) {
    float2 f; asm("mov.b64 {%0,%1}, %2;" : "=f"(f.x), "=f"(f.y) : "l"(p)); return f;
}

// ---------------------------------------------------------------------------
__global__ void build_cp_kernel(const float* __restrict__ rel_h,
                                const float* __restrict__ rel_w)
{
    int idx = blockIdx.x * blockDim.x + threadIdx.x;
    if (idx >= Hn * SQn) return;
    int t = idx % Dn;
    int p = (idx / Dn) % Tn;
    int h = idx / (Dn * Tn);
    g_cp[idx] = rel_h[(h * Dn + t) * HGTn + (p / WIDn)]
              + rel_w[(h * Dn + t) * WIDn + (p % WIDn)];
}

// ---------------------------------------------------------------------------
// NT SGEMM, CTA 128x128, BK=16, 256 thr, per-thread 8x8 (m packed in pairs).
// OUT_SEL: 0 -> row-major outp (A = g_o); 1/2/3 -> scatter g_q/g_k/g_v.
// ---------------------------------------------------------------------------
template <int OUT_SEL>
__global__ void __launch_bounds__(256) proj_kernel(const float* __restrict__ Ain,
                                                   const float* __restrict__ W,
                                                   const float* __restrict__ bias,
                                                   float* __restrict__ outp)
{
    const float* __restrict__ A = (OUT_SEL == 0) ? g_o : Ain;

    __shared__ __align__(16) float As[16][130];   // [k][m]
    __shared__ __align__(16) float Bs[16][130];   // [k][n]

    const int tid = threadIdx.x;
    const int m0 = blockIdx.y * 128;
    const int n0 = blockIdx.x * 128;
    const int ty = tid >> 4;          // 0..15
    const int tx = tid & 15;          // 0..15
    const int lr = tid >> 2;          // 0..63
    const int lc4 = (tid & 3) * 4;    // 0,4,8,12

    u64 acc[4][8];
#pragma unroll
    for (int i = 0; i < 4; i++)
#pragma unroll
        for (int j = 0; j < 8; j++) acc[i][j] = 0ull;

    for (int kt = 0; kt < 49; ++kt) {
        const int k0 = kt * 16;
        float4 a0 = *(const float4*)(A + (size_t)(m0 + lr) * Cn + k0 + lc4);
        float4 a1 = *(const float4*)(A + (size_t)(m0 + lr + 64) * Cn + k0 + lc4);
        float4 b0 = (n0 + lr < Cn)
                        ? *(const float4*)(W + (size_t)(n0 + lr) * Cn + k0 + lc4) : f4zero();
        float4 b1 = (n0 + lr + 64 < Cn)
                        ? *(const float4*)(W + (size_t)(n0 + lr + 64) * Cn + k0 + lc4) : f4zero();
        __syncthreads();
        As[lc4 + 0][lr] = a0.x; As[lc4 + 1][lr] = a0.y; As[lc4 + 2][lr] = a0.z; As[lc4 + 3][lr] = a0.w;
        As[lc4 + 0][lr + 64] = a1.x; As[lc4 + 1][lr + 64] = a1.y; As[lc4 + 2][lr + 64] = a1.z; As[lc4 + 3][lr + 64] = a1.w;
        Bs[lc4 + 0][lr] = b0.x; Bs[lc4 + 1][lr] = b0.y; Bs[lc4 + 2][lr] = b0.z; Bs[lc4 + 3][lr] = b0.w;
        Bs[lc4 + 0][lr + 64] = b1.x; Bs[lc4 + 1][lr + 64] = b1.y; Bs[lc4 + 2][lr + 64] = b1.z; Bs[lc4 + 3][lr + 64] = b1.w;
        __syncthreads();
#pragma unroll
        for (int k = 0; k < 16; k++) {
            u64 av[4];
#pragma unroll
            for (int p = 0; p < 4; p++)
                av[p] = *(const u64*)&As[k][ty * 2 + p * 32];
#pragma unroll
            for (int jj = 0; jj < 8; jj++) {
                u64 bd = dup2(Bs[k][tx + jj * 16]);
#pragma unroll
                for (int p = 0; p < 4; p++) ffma2(acc[p][jj], av[p], bd);
            }
        }
    }

#pragma unroll
    for (int jj = 0; jj < 8; jj++) {
        int gc = n0 + tx + jj * 16;
        if (gc >= Cn) continue;
        float bv = bias[gc];
#pragma unroll
        for (int p = 0; p < 4; p++) {
            float2 v = unpack2(acc[p][jj]);
            int gr = m0 + ty * 2 + p * 32;
            float v0 = v.x + bv, v1 = v.y + bv;
            if (OUT_SEL == 0) {
                outp[(size_t)gr * Cn + gc] = v0;
                outp[(size_t)(gr + 1) * Cn + gc] = v1;
            } else {
                float* dst = (OUT_SEL == 1) ? g_q : (OUT_SEL == 2) ? g_k : g_v;
                int h = gc / Dn, dd = gc % Dn;
                int b0_ = gr / Tn, n0_ = gr % Tn;
                dst[((size_t)(b0_ * Hn + h) * Tn + n0_) * Dn + dd] = v0;
                int b1_ = (gr + 1) / Tn, n1_ = (gr + 1) % Tn;
                dst[((size_t)(b1_ * Hn + h) * Tn + n1_) * Dn + dd] = v1;
            }
        }
    }
}

// ---------------------------------------------------------------------------
// Logits: L[p][m] = sum_t Q[p][t]*K[m][t]/14 + sum_t C[p][t]*Q[t][m]
// CTA 128x128 over (p,m), BK=16 over t (13 tiles, float4-granular pred).
// ---------------------------------------------------------------------------
__global__ void __launch_bounds__(256) logits_kernel()
{
    const int bh = blockIdx.z;
    const int h  = bh & 3;
    const int p0 = blockIdx.y * 128;
    const int m0 = blockIdx.x * 128;
    const float* __restrict__ Q  = g_q  + (size_t)bh * SQn;
    const float* __restrict__ Kp = g_k  + (size_t)bh * SQn;
    const float* __restrict__ CP = g_cp + (size_t)h  * SQn;

    __shared__ __align__(16) float Aq[16][130];   // [t][p]
    __shared__ __align__(16) float Ac[16][130];   // [t][p]
    __shared__ __align__(16) float Bk[16][130];   // [t][m], pre-scaled 1/14
    __shared__ __align__(16) float Bq[16][132];   // [t][m] (Q^T side)

    const int tid = threadIdx.x;
    const int ty = tid >> 4, tx = tid & 15;
    const int lr = tid >> 2, lc4 = (tid & 3) * 4;
    const int cc = tid >> 4;            // 0..15 (t row for Bq loads)
    const int m4 = (tid & 15) * 4;      // 0..60
    const float invs = 1.0f / 14.0f;

    u64 acc[4][8];
#pragma unroll
    for (int i = 0; i < 4; i++)
#pragma unroll
        for (int j = 0; j < 8; j++) acc[i][j] = 0ull;

    for (int kt = 0; kt < 13; ++kt) {
        const int t0 = kt * 16;
        const bool kv = (t0 + lc4) < Tn;   // 196 % 4 == 0 -> whole float4 valid
        float4 qa0 = (kv && p0 + lr < Tn)      ? *(const float4*)(Q  + (p0 + lr) * Dn + t0 + lc4) : f4zero();
        float4 qa1 = (kv && p0 + lr + 64 < Tn) ? *(const float4*)(Q  + (p0 + lr + 64) * Dn + t0 + lc4) : f4zero();
        float4 ca0 = (kv && p0 + lr < Tn)      ? *(const float4*)(CP + (p0 + lr) * Dn + t0 + lc4) : f4zero();
        float4 ca1 = (kv && p0 + lr + 64 < Tn) ? *(const float4*)(CP + (p0 + lr + 64) * Dn + t0 + lc4) : f4zero();
        float4 kb0 = (kv && m0 + lr < Tn)      ? *(const float4*)(Kp + (m0 + lr) * Dn + t0 + lc4) : f4zero();
        float4 kb1 = (kv && m0 + lr + 64 < Tn) ? *(const float4*)(Kp + (m0 + lr + 64) * Dn + t0 + lc4) : f4zero();
        float4 qb0 = (t0 + cc < Tn && m0 + m4 < Tn)      ? *(const float4*)(Q + (t0 + cc) * Dn + m0 + m4) : f4zero();
        float4 qb1 = (t0 + cc < Tn && m0 + m4 + 64 < Tn) ? *(const float4*)(Q + (t0 + cc) * Dn + m0 + m4 + 64) : f4zero();
        __syncthreads();
        Aq[lc4 + 0][lr] = qa0.x; Aq[lc4 + 1][lr] = qa0.y; Aq[lc4 + 2][lr] = qa0.z; Aq[lc4 + 3][lr] = qa0.w;
        Aq[lc4 + 0][lr + 64] = qa1.x; Aq[lc4 + 1][lr + 64] = qa1.y; Aq[lc4 + 2][lr + 64] = qa1.z; Aq[lc4 + 3][lr + 64] = qa1.w;
        Ac[lc4 + 0][lr] = ca0.x; Ac[lc4 + 1][lr] = ca0.y; Ac[lc4 + 2][lr] = ca0.z; Ac[lc4 + 3][lr] = ca0.w;
        Ac[lc4 + 0][lr + 64] = ca1.x; Ac[lc4 + 1][lr + 64] = ca1.y; Ac[lc4 + 2][lr + 64] = ca1.z; Ac[lc4 + 3][lr + 64] = ca1.w;
        Bk[lc4 + 0][lr] = kb0.x * invs; Bk[lc4 + 1][lr] = kb0.y * invs; Bk[lc4 + 2][lr] = kb0.z * invs; Bk[lc4 + 3][lr] = kb0.w * invs;
        Bk[lc4 + 0][lr + 64] = kb1.x * invs; Bk[lc4 + 1][lr + 64] = kb1.y * invs; Bk[lc4 + 2][lr + 64] = kb1.z * invs; Bk[lc4 + 3][lr + 64] = kb1.w * invs;
        *(float4*)&Bq[cc][m4] = qb0;
        *(float4*)&Bq[cc][m4 + 64] = qb1;
        __syncthreads();
#pragma unroll
        for (int k = 0; k < 16; k++) {
            u64 aqv[4], acv[4];
#pragma unroll
            for (int p = 0; p < 4; p++) {
                aqv[p] = *(const u64*)&Aq[k][ty * 2 + p * 32];
                acv[p] = *(const u64*)&Ac[k][ty * 2 + p * 32];
            }
#pragma unroll
            for (int jj = 0; jj < 8; jj++) {
                u64 bkd = dup2(Bk[k][tx + jj * 16]);
                u64 bqd = dup2(Bq[k][tx + jj * 16]);
#pragma unroll
                for (int p = 0; p < 4; p++) {
                    ffma2(acc[p][jj], aqv[p], bkd);
                    ffma2(acc[p][jj], acv[p], bqd);
                }
            }
        }
    }

    float* __restrict__ L = g_l + (size_t)bh * SQn;
#pragma unroll
    for (int jj = 0; jj < 8; jj++) {
        int m = m0 + tx + jj * 16;
        if (m >= Tn) continue;
#pragma unroll
        for (int p = 0; p < 4; p++) {
            float2 v = unpack2(acc[p][jj]);
            int pr = p0 + ty * 2 + p * 32;
            if (pr < Tn)     L[pr * Tn + m] = v.x;
            if (pr + 1 < Tn) L[(pr + 1) * Tn + m] = v.y;
        }
    }
}

// ---------------------------------------------------------------------------
__global__ void __launch_bounds__(256) softmax_kernel()
{
    int gw = (blockIdx.x * blockDim.x + threadIdx.x) >> 5;
    int lane = threadIdx.x & 31;
    if (gw >= BHn * Tn) return;
    float* __restrict__ row = g_l + (size_t)gw * Tn;

    float v[7];
    float mx = -3.0e38f;
#pragma unroll
    for (int w = 0; w < 7; w++) {
        int idx = lane + w * 32;
        v[w] = (idx < Tn) ? row[idx] : -3.0e38f;
        mx = fmaxf(mx, v[w]);
    }
#pragma unroll
    for (int o = 16; o > 0; o >>= 1) mx = fmaxf(mx, __shfl_xor_sync(0xffffffffu, mx, o));

    float s = 0.f;
#pragma unroll
    for (int w = 0; w < 7; w++) {
        int idx = lane + w * 32;
        float e = (idx < Tn) ? __expf(v[w] - mx) : 0.f;
        v[w] = e; s += e;
    }
#pragma unroll
    for (int o = 16; o > 0; o >>= 1) s += __shfl_xor_sync(0xffffffffu, s, o);

    float inv = 1.0f / s;
#pragma unroll
    for (int w = 0; w < 7; w++) {
        int idx = lane + w * 32;
        if (idx < Tn) row[idx] = v[w] * inv;
    }
}

// ---------------------------------------------------------------------------
// O[bh][p][dd] = sum_m A[bh][p][m] * V[bh][m][dd]  -> g_o (b,n,c) layout
// CTA 128x128 over (p,d), BK=16 over m (13 tiles).
// ---------------------------------------------------------------------------
__global__ void __launch_bounds__(256) av_kernel()
{
    const int bh = blockIdx.z;
    const int b = bh >> 2, h = bh & 3;
    const int p0 = blockIdx.y * 128;
    const int d0 = blockIdx.x * 128;
    const float* __restrict__ Att = g_l + (size_t)bh * SQn;
    const float* __restrict__ V   = g_v + (size_t)bh * SQn;

    __shared__ __align__(16) float As[16][130];   // [m][p]
    __shared__ __align__(16) float Bs[16][132];   // [m][d]

    const int tid = threadIdx.x;
    const int ty = tid >> 4, tx = tid & 15;
    const int lr = tid >> 2, lc4 = (tid & 3) * 4;
    const int cc = tid >> 4;
    const int m4 = (tid & 15) * 4;

    u64 acc[4][8];
#pragma unroll
    for (int i = 0; i < 4; i++)
#pragma unroll
        for (int j = 0; j < 8; j++) acc[i][j] = 0ull;

    for (int kt = 0; kt < 13; ++kt) {
        const int t0 = kt * 16;
        const bool kv = (t0 + lc4) < Tn;
        float4 a0 = (kv && p0 + lr < Tn)      ? *(const float4*)(Att + (p0 + lr) * Tn + t0 + lc4) : f4zero();
        float4 a1 = (kv && p0 + lr + 64 < Tn) ? *(const float4*)(Att + (p0 + lr + 64) * Tn + t0 + lc4) : f4zero();
        float4 b0 = (t0 + cc < Tn && d0 + m4 < Dn)      ? *(const float4*)(V + (t0 + cc) * Dn + d0 + m4) : f4zero();
        float4 b1 = (t0 + cc < Tn && d0 + m4 + 64 < Dn) ? *(const float4*)(V + (t0 + cc) * Dn + d0 + m4 + 64) : f4zero();
        __syncthreads();
        As[lc4 + 0][lr] = a0.x; As[lc4 + 1][lr] = a0.y; As[lc4 + 2][lr] = a0.z; As[lc4 + 3][lr] = a0.w;
        As[lc4 + 0][lr + 64] = a1.x; As[lc4 + 1][lr + 64] = a1.y; As[lc4 + 2][lr + 64] = a1.z; As[lc4 + 3][lr + 64] = a1.w;
        *(float4*)&Bs[cc][m4] = b0;
        *(float4*)&Bs[cc][m4 + 64] = b1;
        __syncthreads();
#pragma unroll
        for (int k = 0; k < 16; k++) {
            u64 av[4];
#pragma unroll
            for (int p = 0; p < 4; p++)
                av[p] = *(const u64*)&As[k][ty * 2 + p * 32];
#pragma unroll
            for (int jj = 0; jj < 8; jj++) {
                u64 bd = dup2(Bs[k][tx + jj * 16]);
#pragma unroll
                for (int p = 0; p < 4; p++) ffma2(acc[p][jj], av[p], bd);
            }
        }
    }

#pragma unroll
    for (int jj = 0; jj < 8; jj++) {
        int dd = d0 + tx + jj * 16;
        if (dd >= Dn) continue;
#pragma unroll
        for (int p = 0; p < 4; p++) {
            float2 v = unpack2(acc[p][jj]);
            int pr = p0 + ty * 2 + p * 32;
            if (pr < Tn)
                g_o[(size_t)(b * Tn + pr) * Cn + h * Dn + dd] = v.x;
            if (pr + 1 < Tn)
                g_o[(size_t)(b * Tn + pr + 1) * Cn + h * Dn + dd] = v.y;
        }
    }
}

// ---------------------------------------------------------------------------
extern "C" void kernel_launch(void* const* d_in, const int* in_sizes, int n_in,
                              void* d_out, int out_size)
{
    const float* x    = (const float*)d_in[0];
    const float* Wq   = (const float*)d_in[1];
    const float* bq   = (const float*)d_in[2];
    const float* Wk   = (const float*)d_in[3];
    const float* bk   = (const float*)d_in[4];
    const float* Wv   = (const float*)d_in[5];
    const float* bv   = (const float*)d_in[6];
    const float* Wo   = (const float*)d_in[7];
    const float* bo   = (const float*)d_in[8];
    const float* relh = (const float*)d_in[9];
    const float* relw = (const float*)d_in[10];
    float* out = (float*)d_out;

    build_cp_kernel<<<(Hn * SQn + 255) / 256, 256>>>(relh, relw);

    dim3 pg(7, 392);   // 7 col tiles of 128 (784 -> 896 predicated), 392 row tiles of 128
    proj_kernel<1><<<pg, 256>>>(x, Wq, bq, nullptr);
    proj_kernel<2><<<pg, 256>>>(x, Wk, bk, nullptr);
    proj_kernel<3><<<pg, 256>>>(x, Wv, bv, nullptr);

    logits_kernel<<<dim3(2, 2, BHn), 256>>>();
    softmax_kernel<<<(BHn * Tn) / 8, 256>>>();
    av_kernel<<<dim3(2, 2, BHn), 256>>>();

    proj_kernel<0><<<pg, 256>>>(nullptr, Wo, bo, out);
}